// round 12
// baseline (speedup 1.0000x reference)
#include <cuda_runtime.h>
#include <cuda_bf16.h>
#include <cstdint>

#define Cc 128
#define Gg 2000

// ---------------- scratch (device globals; no allocation) ----------------
__device__ float d_ce_g[Cc * 64];
__device__ float d_A_g[Cc * 256];
__device__ float d_B_g[Gg * 256];
__device__ float d_p_g[Gg * 256];
__device__ float d_q_g[Gg * 256];
__device__ float d_cg_g[Gg];
__device__ float d_x3_g[Gg * Cc];
__device__ __nv_bfloat16 d_Wt16[256 * 256];   // W2a^T bf16 [n][k]

__device__ __forceinline__ float eluf(float x) {
    return x > 0.f ? x : (__expf(x) - 1.f);
}
// branchless exact elu
__device__ __forceinline__ float melu(float x) {
    return fmaxf(x, 0.f) + __expf(fminf(x, 0.f)) - 1.f;
}

__device__ __forceinline__ void mma_bf16(float* acc, const unsigned* a, const unsigned* b) {
    asm volatile(
        "mma.sync.aligned.m16n8k16.row.col.f32.bf16.bf16.f32 "
        "{%0,%1,%2,%3}, {%4,%5,%6,%7}, {%8,%9}, {%0,%1,%2,%3};"
        : "+f"(acc[0]), "+f"(acc[1]), "+f"(acc[2]), "+f"(acc[3])
        : "r"(a[0]), "r"(a[1]), "r"(a[2]), "r"(a[3]), "r"(b[0]), "r"(b[1]));
}
__device__ __forceinline__ void ldsm4(unsigned& r0, unsigned& r1, unsigned& r2, unsigned& r3,
                                      uint32_t addr) {
    asm volatile("ldmatrix.sync.aligned.m8n8.x4.shared.b16 {%0,%1,%2,%3}, [%4];"
                 : "=r"(r0), "=r"(r1), "=r"(r2), "=r"(r3) : "r"(addr));
}
__device__ __forceinline__ uint32_t smem_u32(const void* p) {
    uint32_t a;
    asm("{ .reg .u64 t; cvta.to.shared.u64 t, %1; cvt.u32.u64 %0, t; }" : "=r"(a) : "l"(p));
    return a;
}
__device__ __forceinline__ void cpasync16(uint32_t dst, const void* src) {
    asm volatile("cp.async.ca.shared.global [%0], [%1], 16;" :: "r"(dst), "l"(src));
}
__device__ __forceinline__ void cp_commit() { asm volatile("cp.async.commit_group;"); }
template <int N> __device__ __forceinline__ void cp_wait() {
    asm volatile("cp.async.wait_group %0;" :: "n"(N));
}

// ---------------- k_ce ----------------
__global__ __launch_bounds__(1024) void k_ce(
    const float* __restrict__ ctrl, const float* __restrict__ ce_w1,
    const float* __restrict__ ce_b1, const float* __restrict__ ce_w2,
    const float* __restrict__ ce_b2)
{
    int c = blockIdx.x, tid = threadIdx.x;
    __shared__ float row[Gg];
    __shared__ float part[4][256];
    __shared__ float h1[256];
    for (int i = tid; i < Gg; i += 1024) row[i] = ctrl[c * Gg + i];
    __syncthreads();
    int sl = tid >> 8, t = tid & 255;
    float acc = 0.f;
    for (int k = sl * 500; k < sl * 500 + 500; k++)
        acc += row[k] * ce_w1[k * 256 + t];
    part[sl][t] = acc;
    __syncthreads();
    if (tid < 256) {
        float v = part[0][tid] + part[1][tid] + part[2][tid] + part[3][tid] + ce_b1[tid];
        h1[tid] = eluf(v);
    }
    __syncthreads();
    if (tid < 256) {
        int s2 = tid >> 6, e = tid & 63;
        float a2 = 0.f;
        for (int h = s2 * 64; h < s2 * 64 + 64; h++)
            a2 += h1[h] * ce_w2[h * 64 + e];
        part[s2][e] = a2;
    }
    __syncthreads();
    if (tid < 64)
        d_ce_g[c * 64 + tid] = part[0][tid] + part[1][tid] + part[2][tid] + part[3][tid] + ce_b2[tid];
}

// ---- k_AT: blocks [0,128) = k_A; blocks [128,192) = W2a transpose->bf16 ----
__global__ __launch_bounds__(256) void k_AT(const float* __restrict__ g_w1,
                                            const float* __restrict__ g_w2)
{
    __shared__ float shb[32][33];
    if (blockIdx.x < 128) {
        int c = blockIdx.x, tid = threadIdx.x;
        float* ces = &shb[0][0];
        if (tid < 64) ces[tid] = d_ce_g[c * 64 + tid];
        __syncthreads();
        float a = 0.f;
#pragma unroll 8
        for (int e = 0; e < 64; e++)
            a += ces[e] * g_w1[(1 + e) * 256 + tid];
        d_A_g[c * 256 + tid] = a;
    } else {
        int bid = blockIdx.x - 128;
        int bx = bid & 7, by = bid >> 3;
        int tx = threadIdx.x & 31, ty = threadIdx.x >> 5;
        int k0 = bx * 32, n0 = by * 32;
#pragma unroll
        for (int p = 0; p < 4; p++)
            shb[ty + 8 * p][tx] = g_w2[(k0 + ty + 8 * p) * 256 + n0 + tx];
        __syncthreads();
#pragma unroll
        for (int p = 0; p < 4; p++)
            d_Wt16[(n0 + ty + 8 * p) * 256 + k0 + tx] = __float2bfloat16(shb[tx][ty + 8 * p]);
    }
}

// ---- k_Bp: B[g,h] (kept in reg) then p[g,h] = mean_c elu(ctrl*r + A + B) ----
__global__ __launch_bounds__(256) void k_Bp(
    const int* __restrict__ gidx, const float* __restrict__ shift_vec,
    const float* __restrict__ gene_table, const float* __restrict__ g_w1,
    const float* __restrict__ g_b1, const float* __restrict__ ctrl)
{
    int g = blockIdx.x, tid = threadIdx.x;
    __shared__ float ges[64];
    __shared__ float shs;
    __shared__ float cs[128];
    int gs = gidx[g];
    if (tid < 64) ges[tid] = gene_table[gs * 64 + tid];
    if (tid == 0) shs = shift_vec[gs];
    if (tid < 128) cs[tid] = ctrl[tid * Gg + gs];
    __syncthreads();
    float a = g_b1[tid] + 128.0f * g_w1[130 * 256 + tid] + shs * g_w1[129 * 256 + tid];
#pragma unroll 8
    for (int e = 0; e < 64; e++)
        a += ges[e] * g_w1[(65 + e) * 256 + tid];
    d_B_g[g * 256 + tid] = a;
    float rv = g_w1[tid];
    float s = 0.f;
#pragma unroll 8
    for (int c = 0; c < 128; c++)
        s += melu(fmaf(cs[c], rv, d_A_g[c * 256 + tid] + a));
    d_p_g[g * 256 + tid] = s * (1.f / 128.f);
}

// ---- k_q: q = p@W2b + b2 ; p2 = p@W2a + q ; cg = sum w3b*elu(p2) + b3 ----
__global__ __launch_bounds__(256) void k_q(
    const float* __restrict__ g_w2, const float* __restrict__ g_b2,
    const float* __restrict__ g_w3, const float* __restrict__ g_b3)
{
    __shared__ float ps[8][256];
    __shared__ float red[8][256];
    int g0 = blockIdx.x * 8, tid = threadIdx.x;
    for (int i = 0; i < 8; i++) ps[i][tid] = d_p_g[(g0 + i) * 256 + tid];
    __syncthreads();
    float qa[8], pa[8];
#pragma unroll
    for (int i = 0; i < 8; i++) { qa[i] = 0.f; pa[i] = 0.f; }
    for (int k = 0; k < 256; k++) {
        float wa = g_w2[k * 256 + tid];
        float wb = g_w2[(256 + k) * 256 + tid];
#pragma unroll
        for (int i = 0; i < 8; i++) {
            float pv = ps[i][k];
            qa[i] = fmaf(pv, wb, qa[i]);
            pa[i] = fmaf(pv, wa, pa[i]);
        }
    }
    float b2v = g_b2[tid];
    float w3bv = g_w3[256 + tid];
#pragma unroll
    for (int i = 0; i < 8; i++) {
        float q = qa[i] + b2v;
        d_q_g[(g0 + i) * 256 + tid] = q;
        float p2 = pa[i] + q;
        red[i][tid] = w3bv * eluf(p2);
    }
    __syncthreads();
    for (int off = 128; off > 0; off >>= 1) {
        if (tid < off)
#pragma unroll
            for (int i = 0; i < 8; i++) red[i][tid] += red[i][tid + off];
        __syncthreads();
    }
    if (tid < 8) d_cg_g[g0 + tid] = red[tid][0] + g_b3[0];
}

// ======= k3: per-(gene, M-quarter) bf16 GEMM, 3 blocks/SM ================
// Block: 32 cells x 256 cols, 8 warps each 32r x 32c.
// W ring 2 x [256 n][20w]; X 2 x [32 c][20w]; A ring 2 x [32 c][36w].
#define WBASE   0
#define WBUFW   5120
#define XBASE   10240
#define XBUFW   640
#define ABASE   11520
#define ABUFW   1152
#define SM_CTRL 13824
#define SM_RS   13856
#define SM_BS   14112
#define SM_QS   14368
#define SM_W3A  14624
#define SM_RR   14880
#define K3_WORDS 15136   // 60544 bytes -> 3 blocks/SM

__global__ __launch_bounds__(256, 3) void k3(
    const float* __restrict__ ctrl, const int* __restrict__ gidx,
    const float* __restrict__ g_w1, const float* __restrict__ g_w3)
{
    extern __shared__ float sm[];
    unsigned* usm = (unsigned*)sm;
    uint32_t sbase = smem_u32(sm);

    int bi = blockIdx.x;
    int g = bi >> 2, mq = bi & 3;
    int tid = threadIdx.x;
    int lane = tid & 31, w = tid >> 5;      // 8 warps; warp w -> cols [32w, 32w+32)
    int lg = lane >> 2, lt = lane & 3;
    int m8 = lane >> 3, r8 = lane & 7;
    int gs = gidx[g];

    // prologue scalars
    if (tid < 32) sm[SM_CTRL + tid] = ctrl[(mq * 32 + tid) * Gg + gs];
    sm[SM_RS + tid]  = g_w1[tid];
    sm[SM_BS + tid]  = d_B_g[g * 256 + tid];
    sm[SM_QS + tid]  = d_q_g[g * 256 + tid];
    sm[SM_W3A + tid] = g_w3[tid];

    auto CPW = [&](int kc, int buf) {
        for (int i = tid; i < 1024; i += 256) {
            int row = i >> 2, seg = i & 3;
            cpasync16(sbase + (WBASE + buf * WBUFW + row * 20 + seg * 4) * 4,
                      d_Wt16 + row * 256 + kc * 32 + seg * 8);
        }
    };
    auto CPA = [&](int kc, int buf) {
        int row = tid >> 3, seg = tid & 7;
        cpasync16(sbase + (ABASE + buf * ABUFW + row * 36 + seg * 4) * 4,
                  d_A_g + (mq * 32 + row) * 256 + kc * 32 + seg * 4);
    };
    auto GENX = [&](int kc, int xbuf) {
        int xw = XBASE + xbuf * XBUFW;
        int ab = ABASE + (kc & 1) * ABUFW;
        int kp = tid & 15, c0 = tid >> 4;
        int h0 = kc * 32 + 2 * kp;
        float2 rsv = *(float2*)(sm + SM_RS + h0);
        float2 bsv = *(float2*)(sm + SM_BS + h0);
#pragma unroll
        for (int j = 0; j < 2; j++) {
            int c = c0 + 16 * j;
            float cv = sm[SM_CTRL + c];
            float2 av = *(float2*)(sm + ab + c * 36 + 2 * kp);
            float v0 = melu(fmaf(cv, rsv.x, av.x + bsv.x));
            float v1 = melu(fmaf(cv, rsv.y, av.y + bsv.y));
            unsigned pr;
            asm("cvt.rn.bf16x2.f32 %0, %1, %2;" : "=r"(pr) : "f"(v1), "f"(v0));
            usm[xw + c * 20 + kp] = pr;
        }
    };

    CPW(0, 0); CPA(0, 0); cp_commit();
    CPW(1, 1); CPA(1, 1); cp_commit();
    cp_wait<1>();        // chunk 0 resident
    __syncthreads();     // prologue + chunk 0 visible
    GENX(0, 0);
    __syncthreads();

    float acc[2][4][4];
#pragma unroll
    for (int i = 0; i < 2; i++)
#pragma unroll
        for (int j = 0; j < 4; j++)
#pragma unroll
            for (int k = 0; k < 4; k++) acc[i][j][k] = 0.f;

#pragma unroll
    for (int kc = 0; kc < 8; kc++) {
        uint32_t xbb = sbase + (XBASE + (kc & 1) * XBUFW) * 4;
        uint32_t wbb = sbase + (WBASE + (kc & 1) * WBUFW) * 4;
#pragma unroll
        for (int ks = 0; ks < 2; ks++) {
            int k0b = ks * 32;
            unsigned a[2][4], b[4][2];
#pragma unroll
            for (int ra = 0; ra < 2; ra++) {
                uint32_t addr = xbb + (ra * 16 + (m8 & 1) * 8 + r8) * 80
                              + k0b + (m8 >> 1) * 16;
                ldsm4(a[ra][0], a[ra][1], a[ra][2], a[ra][3], addr);
            }
#pragma unroll
            for (int cbp = 0; cbp < 2; cbp++) {
                uint32_t addr = wbb + (w * 32 + (2 * cbp + (m8 >> 1)) * 8 + r8) * 80
                              + k0b + (m8 & 1) * 16;
                ldsm4(b[2 * cbp][0], b[2 * cbp][1], b[2 * cbp + 1][0], b[2 * cbp + 1][1], addr);
            }
#pragma unroll
            for (int ra = 0; ra < 2; ra++)
#pragma unroll
                for (int cb = 0; cb < 4; cb++)
                    mma_bf16(acc[ra][cb], a[ra], b[cb]);
        }
        if (kc < 7) {
            cp_wait<0>();          // chunk kc+1 (W+A) fully resident
            GENX(kc + 1, (kc + 1) & 1);
        }
        __syncthreads();
        if (kc < 6) {
            CPW(kc + 2, kc & 1);   // W buf kc&1 free (MMA(kc) done block-wide)
            CPA(kc + 2, kc & 1);   // A buf kc&1 free (GENX(kc) done last iter)
            cp_commit();
        }
    }

    // -------- epilogue: row sums of w3a * elu(x2 + q) --------
    float rsum[2][2];
    rsum[0][0] = rsum[0][1] = rsum[1][0] = rsum[1][1] = 0.f;
#pragma unroll
    for (int ra = 0; ra < 2; ra++) {
#pragma unroll
        for (int cb = 0; cb < 4; cb++) {
#pragma unroll
            for (int jj = 0; jj < 4; jj++) {
                int col = w * 32 + cb * 8 + 2 * lt + (jj & 1);
                float v = acc[ra][cb][jj] + sm[SM_QS + col];
                rsum[ra][jj >> 1] += sm[SM_W3A + col] * melu(v);
            }
        }
    }
#pragma unroll
    for (int m = 1; m <= 2; m <<= 1)
#pragma unroll
        for (int ra = 0; ra < 2; ra++) {
            rsum[ra][0] += __shfl_xor_sync(0xffffffffu, rsum[ra][0], m);
            rsum[ra][1] += __shfl_xor_sync(0xffffffffu, rsum[ra][1], m);
        }
    if (lt == 0) {
#pragma unroll
        for (int ra = 0; ra < 2; ra++) {
            sm[SM_RR + w * 32 + ra * 16 + lg]     = rsum[ra][0];
            sm[SM_RR + w * 32 + ra * 16 + 8 + lg] = rsum[ra][1];
        }
    }
    __syncthreads();
    if (tid < 32) {
        float s = 0.f;
#pragma unroll
        for (int ww = 0; ww < 8; ww++) s += sm[SM_RR + ww * 32 + tid];
        d_x3_g[g * 128 + mq * 32 + tid] = s;
    }
}

// ---- k4: + cgene, softmax over cells ----
__global__ __launch_bounds__(128) void k4(float* __restrict__ out)
{
    int g = blockIdx.x, tid = threadIdx.x;
    __shared__ float buf[128];
    float v = d_x3_g[g * 128 + tid] + d_cg_g[g];
    buf[tid] = v;
    __syncthreads();
    for (int off = 64; off > 0; off >>= 1) {
        if (tid < off) buf[tid] = fmaxf(buf[tid], buf[tid + off]);
        __syncthreads();
    }
    float m = buf[0];
    __syncthreads();
    float e = __expf(v - m);
    buf[tid] = e;
    __syncthreads();
    for (int off = 64; off > 0; off >>= 1) {
        if (tid < off) buf[tid] += buf[tid + off];
        __syncthreads();
    }
    out[tid * Gg + g] = e / buf[0];
}

// -------------------------------------------------------------------------
extern "C" void kernel_launch(void* const* d_in, const int* in_sizes, int n_in,
                              void* d_out, int out_size)
{
    const float* ctrl       = (const float*)d_in[0];
    const float* shift_vec  = (const float*)d_in[1];
    const int*   gidx       = (const int*)d_in[2];
    const float* ce_w1      = (const float*)d_in[3];
    const float* ce_b1      = (const float*)d_in[4];
    const float* ce_w2      = (const float*)d_in[5];
    const float* ce_b2      = (const float*)d_in[6];
    const float* gene_table = (const float*)d_in[7];
    const float* g_w1       = (const float*)d_in[8];
    const float* g_b1       = (const float*)d_in[9];
    const float* g_w2       = (const float*)d_in[10];
    const float* g_b2       = (const float*)d_in[11];
    const float* g_w3       = (const float*)d_in[12];
    const float* g_b3       = (const float*)d_in[13];
    float* out = (float*)d_out;

    cudaFuncSetAttribute(k3, cudaFuncAttributeMaxDynamicSharedMemorySize,
                         K3_WORDS * (int)sizeof(float));

    k_ce<<<Cc, 1024>>>(ctrl, ce_w1, ce_b1, ce_w2, ce_b2);
    k_AT<<<192, 256>>>(g_w1, g_w2);
    k_Bp<<<Gg, 256>>>(gidx, shift_vec, gene_table, g_w1, g_b1, ctrl);
    k_q<<<Gg / 8, 256>>>(g_w2, g_b2, g_w3, g_b3);
    k3<<<4 * Gg, 256, K3_WORDS * sizeof(float)>>>(ctrl, gidx, g_w1, g_w3);
    k4<<<Gg, 128>>>(out);
}

// round 13
// speedup vs baseline: 1.2463x; 1.2463x over previous
#include <cuda_runtime.h>
#include <cuda_bf16.h>
#include <cstdint>

#define Cc 128
#define Gg 2000

// ---------------- scratch (device globals; no allocation) ----------------
__device__ float d_ce_g[Cc * 64];
__device__ float d_A_g[Cc * 256];
__device__ float d_B_g[Gg * 256];
__device__ float d_p_g[Gg * 256];
__device__ float d_q_g[Gg * 256];
__device__ float d_cg_g[Gg];
__device__ float d_x3_g[Gg * Cc];
__device__ __nv_bfloat16 d_Wt16[256 * 256];   // W2a^T bf16 [n][k]

__device__ __forceinline__ float eluf(float x) {
    return x > 0.f ? x : (__expf(x) - 1.f);
}
// branchless exact elu
__device__ __forceinline__ float melu(float x) {
    return fmaxf(x, 0.f) + __expf(fminf(x, 0.f)) - 1.f;
}

__device__ __forceinline__ void mma_bf16(float* acc, const unsigned* a, const unsigned* b) {
    asm volatile(
        "mma.sync.aligned.m16n8k16.row.col.f32.bf16.bf16.f32 "
        "{%0,%1,%2,%3}, {%4,%5,%6,%7}, {%8,%9}, {%0,%1,%2,%3};"
        : "+f"(acc[0]), "+f"(acc[1]), "+f"(acc[2]), "+f"(acc[3])
        : "r"(a[0]), "r"(a[1]), "r"(a[2]), "r"(a[3]), "r"(b[0]), "r"(b[1]));
}
__device__ __forceinline__ void ldsm4(unsigned& r0, unsigned& r1, unsigned& r2, unsigned& r3,
                                      uint32_t addr) {
    asm volatile("ldmatrix.sync.aligned.m8n8.x4.shared.b16 {%0,%1,%2,%3}, [%4];"
                 : "=r"(r0), "=r"(r1), "=r"(r2), "=r"(r3) : "r"(addr));
}
__device__ __forceinline__ uint32_t smem_u32(const void* p) {
    uint32_t a;
    asm("{ .reg .u64 t; cvta.to.shared.u64 t, %1; cvt.u32.u64 %0, t; }" : "=r"(a) : "l"(p));
    return a;
}
__device__ __forceinline__ void cpasync16(uint32_t dst, const void* src) {
    asm volatile("cp.async.ca.shared.global [%0], [%1], 16;" :: "r"(dst), "l"(src));
}
__device__ __forceinline__ void cp_commit() { asm volatile("cp.async.commit_group;"); }
template <int N> __device__ __forceinline__ void cp_wait() {
    asm volatile("cp.async.wait_group %0;" :: "n"(N));
}

// ---------------- k_ce ----------------
__global__ __launch_bounds__(1024) void k_ce(
    const float* __restrict__ ctrl, const float* __restrict__ ce_w1,
    const float* __restrict__ ce_b1, const float* __restrict__ ce_w2,
    const float* __restrict__ ce_b2)
{
    int c = blockIdx.x, tid = threadIdx.x;
    __shared__ float row[Gg];
    __shared__ float part[4][256];
    __shared__ float h1[256];
    for (int i = tid; i < Gg; i += 1024) row[i] = ctrl[c * Gg + i];
    __syncthreads();
    int sl = tid >> 8, t = tid & 255;
    float acc = 0.f;
    for (int k = sl * 500; k < sl * 500 + 500; k++)
        acc += row[k] * ce_w1[k * 256 + t];
    part[sl][t] = acc;
    __syncthreads();
    if (tid < 256) {
        float v = part[0][tid] + part[1][tid] + part[2][tid] + part[3][tid] + ce_b1[tid];
        h1[tid] = eluf(v);
    }
    __syncthreads();
    if (tid < 256) {
        int s2 = tid >> 6, e = tid & 63;
        float a2 = 0.f;
        for (int h = s2 * 64; h < s2 * 64 + 64; h++)
            a2 += h1[h] * ce_w2[h * 64 + e];
        part[s2][e] = a2;
    }
    __syncthreads();
    if (tid < 64)
        d_ce_g[c * 64 + tid] = part[0][tid] + part[1][tid] + part[2][tid] + part[3][tid] + ce_b2[tid];
}

// ---- k_AT: blocks [0,128) = k_A; blocks [128,192) = W2a transpose->bf16 ----
__global__ __launch_bounds__(256) void k_AT(const float* __restrict__ g_w1,
                                            const float* __restrict__ g_w2)
{
    __shared__ float shb[32][33];
    if (blockIdx.x < 128) {
        int c = blockIdx.x, tid = threadIdx.x;
        float* ces = &shb[0][0];
        if (tid < 64) ces[tid] = d_ce_g[c * 64 + tid];
        __syncthreads();
        float a = 0.f;
#pragma unroll 8
        for (int e = 0; e < 64; e++)
            a += ces[e] * g_w1[(1 + e) * 256 + tid];
        d_A_g[c * 256 + tid] = a;
    } else {
        int bid = blockIdx.x - 128;
        int bx = bid & 7, by = bid >> 3;
        int tx = threadIdx.x & 31, ty = threadIdx.x >> 5;
        int k0 = bx * 32, n0 = by * 32;
#pragma unroll
        for (int p = 0; p < 4; p++)
            shb[ty + 8 * p][tx] = g_w2[(k0 + ty + 8 * p) * 256 + n0 + tx];
        __syncthreads();
#pragma unroll
        for (int p = 0; p < 4; p++)
            d_Wt16[(n0 + ty + 8 * p) * 256 + k0 + tx] = __float2bfloat16(shb[tx][ty + 8 * p]);
    }
}

// ---------------- k_B ----------------
__global__ void k_B(const int* __restrict__ gidx, const float* __restrict__ shift_vec,
                    const float* __restrict__ gene_table, const float* __restrict__ g_w1,
                    const float* __restrict__ g_b1)
{
    int g = blockIdx.x, tid = threadIdx.x;
    __shared__ float ges[64];
    __shared__ float shs;
    int gs = gidx[g];
    if (tid < 64) ges[tid] = gene_table[gs * 64 + tid];
    if (tid == 0) shs = shift_vec[gs];
    __syncthreads();
    float a = g_b1[tid] + 128.0f * g_w1[130 * 256 + tid] + shs * g_w1[129 * 256 + tid];
#pragma unroll 8
    for (int e = 0; e < 64; e++)
        a += ges[e] * g_w1[(65 + e) * 256 + tid];
    d_B_g[g * 256 + tid] = a;
}

// ---- k_p: p[g,h] = mean_c elu(ctrl*r + A + B) ----
__global__ __launch_bounds__(256) void k_p(
    const float* __restrict__ ctrl, const int* __restrict__ gidx,
    const float* __restrict__ g_w1)
{
    int g = blockIdx.x, tid = threadIdx.x;
    __shared__ float cs[128];
    int gs = gidx[g];
    if (tid < 128) cs[tid] = ctrl[tid * Gg + gs];
    __syncthreads();
    float rv = g_w1[tid];
    float Bv = d_B_g[g * 256 + tid];
    float s = 0.f;
#pragma unroll 8
    for (int c = 0; c < 128; c++)
        s += melu(fmaf(cs[c], rv, d_A_g[c * 256 + tid] + Bv));
    d_p_g[g * 256 + tid] = s * (1.f / 128.f);
}

// ---- k_q (split-k, 512 thr): q = p@W2b + b2 ; p2 = p@W2a + q ; cgene ----
__global__ __launch_bounds__(512) void k_q(
    const float* __restrict__ g_w2, const float* __restrict__ g_b2,
    const float* __restrict__ g_w3, const float* __restrict__ g_b3)
{
    __shared__ float ps[8][256];
    __shared__ float qpart[2][8][256];
    __shared__ float ppart[2][8][256];
    int g0 = blockIdx.x * 8, tid = threadIdx.x;
    for (int i = tid; i < 2048; i += 512)
        ps[i >> 8][i & 255] = d_p_g[(g0 + (i >> 8)) * 256 + (i & 255)];
    __syncthreads();
    int n = tid & 255, kh = tid >> 8;
    float qa[8], pa[8];
#pragma unroll
    for (int i = 0; i < 8; i++) { qa[i] = 0.f; pa[i] = 0.f; }
    for (int k = kh * 128; k < kh * 128 + 128; k++) {
        float wa = g_w2[k * 256 + n];
        float wb = g_w2[(256 + k) * 256 + n];
#pragma unroll
        for (int i = 0; i < 8; i++) {
            float pv = ps[i][k];
            qa[i] = fmaf(pv, wb, qa[i]);
            pa[i] = fmaf(pv, wa, pa[i]);
        }
    }
#pragma unroll
    for (int i = 0; i < 8; i++) {
        qpart[kh][i][n] = qa[i];
        ppart[kh][i][n] = pa[i];
    }
    __syncthreads();
    if (tid < 256) {
        float b2v = g_b2[tid];
        float w3bv = g_w3[256 + tid];
#pragma unroll
        for (int i = 0; i < 8; i++) {
            float q = qpart[0][i][tid] + qpart[1][i][tid] + b2v;
            d_q_g[(g0 + i) * 256 + tid] = q;
            float p2 = ppart[0][i][tid] + ppart[1][i][tid] + q;
            ps[i][tid] = w3bv * eluf(p2);   // reuse ps as reduce buffer
        }
    }
    __syncthreads();
    for (int off = 128; off > 0; off >>= 1) {
        if (tid < off)
#pragma unroll
            for (int i = 0; i < 8; i++) ps[i][tid] += ps[i][tid + off];
        __syncthreads();
    }
    if (tid < 8) d_cg_g[g0 + tid] = ps[tid][0] + g_b3[0];
}

// ======= k3: per-(gene, M-half) bf16 GEMM via ldmatrix + mma.m16n8k16 =====
// (exact R10 configuration: 274.9 us total)
#define WBASE   0
#define WBUFW   5120
#define XBASE   15360
#define XBUFW   1280
#define ABASE   17920
#define ABUFW   2304
#define SM_CTRL 22528
#define SM_RS   22592
#define SM_BS   22848
#define SM_QS   23104
#define SM_W3A  23360
#define SM_RR   23616
#define K3_WORDS 23872   // 95488 bytes

__global__ __launch_bounds__(256, 2) void k3(
    const float* __restrict__ ctrl, const int* __restrict__ gidx,
    const float* __restrict__ g_w1, const float* __restrict__ g_w3)
{
    extern __shared__ float sm[];
    unsigned* usm = (unsigned*)sm;
    uint32_t sbase = smem_u32(sm);

    int bi = blockIdx.x;
    int g = bi >> 1, mh = bi & 1;
    int tid = threadIdx.x;
    int lane = tid & 31, w = tid >> 5;
    int lg = lane >> 2, lt = lane & 3;
    int wr = w >> 2, wc = w & 3;          // 2 x 4 warps; warp tile 32 rows x 64 cols
    int m8 = lane >> 3, r8 = lane & 7;
    int gs = gidx[g];

    // prologue scalars
    if (tid < 64) sm[SM_CTRL + tid] = ctrl[(mh * 64 + tid) * Gg + gs];
    sm[SM_RS + tid]  = g_w1[tid];
    sm[SM_BS + tid]  = d_B_g[g * 256 + tid];
    sm[SM_QS + tid]  = d_q_g[g * 256 + tid];
    sm[SM_W3A + tid] = g_w3[tid];

    auto CPW = [&](int kc, int buf) {
        for (int i = tid; i < 1024; i += 256) {
            int row = i >> 2, seg = i & 3;
            cpasync16(sbase + (WBASE + buf * WBUFW + row * 20 + seg * 4) * 4,
                      d_Wt16 + row * 256 + kc * 32 + seg * 8);
        }
    };
    auto CPA = [&](int kc, int buf) {
        for (int i = tid; i < 512; i += 256) {
            int row = i >> 3, seg = i & 7;
            cpasync16(sbase + (ABASE + buf * ABUFW + row * 36 + seg * 4) * 4,
                      d_A_g + (mh * 64 + row) * 256 + kc * 32 + seg * 4);
        }
    };
    auto GENX = [&](int kc, int xbuf) {
        int xw = XBASE + xbuf * XBUFW;
        int ab = ABASE + (kc & 1) * ABUFW;
        int kp = tid & 15, cb0 = tid >> 4;
        int h0 = kc * 32 + 2 * kp;
        float2 rsv = *(float2*)(sm + SM_RS + h0);
        float2 bsv = *(float2*)(sm + SM_BS + h0);
#pragma unroll
        for (int j = 0; j < 4; j++) {
            int c = cb0 + 16 * j;
            float cv = sm[SM_CTRL + c];
            float2 av = *(float2*)(sm + ab + c * 36 + 2 * kp);
            float v0 = melu(fmaf(cv, rsv.x, av.x + bsv.x));
            float v1 = melu(fmaf(cv, rsv.y, av.y + bsv.y));
            unsigned pr;
            asm("cvt.rn.bf16x2.f32 %0, %1, %2;" : "=r"(pr) : "f"(v1), "f"(v0));
            usm[xw + c * 20 + kp] = pr;
        }
    };

    CPW(0, 0); CPA(0, 0); cp_commit();
    CPW(1, 1); CPA(1, 1); cp_commit();
    cp_wait<1>();
    __syncthreads();     // scalars + chunk-0 copies visible
    GENX(0, 0);
    __syncthreads();

    float acc[2][8][4];
#pragma unroll
    for (int i = 0; i < 2; i++)
#pragma unroll
        for (int j = 0; j < 8; j++)
#pragma unroll
            for (int k = 0; k < 4; k++) acc[i][j][k] = 0.f;

#pragma unroll
    for (int kc = 0; kc < 8; kc++) {
        uint32_t xbb = sbase + (XBASE + (kc & 1) * XBUFW) * 4;
        uint32_t wbb = sbase + (WBASE + (kc % 3) * WBUFW) * 4;
#pragma unroll
        for (int ks = 0; ks < 2; ks++) {
            int k0b = ks * 32;
            unsigned a[2][4], b[8][2];
#pragma unroll
            for (int ra = 0; ra < 2; ra++) {
                uint32_t addr = xbb + (wr * 32 + ra * 16 + (m8 & 1) * 8 + r8) * 80
                              + k0b + (m8 >> 1) * 16;
                ldsm4(a[ra][0], a[ra][1], a[ra][2], a[ra][3], addr);
            }
#pragma unroll
            for (int cbp = 0; cbp < 4; cbp++) {
                uint32_t addr = wbb + (wc * 64 + (2 * cbp + (m8 >> 1)) * 8 + r8) * 80
                              + k0b + (m8 & 1) * 16;
                ldsm4(b[2 * cbp][0], b[2 * cbp][1], b[2 * cbp + 1][0], b[2 * cbp + 1][1], addr);
            }
#pragma unroll
            for (int ra = 0; ra < 2; ra++)
#pragma unroll
                for (int cb = 0; cb < 8; cb++)
                    mma_bf16(acc[ra][cb], a[ra], b[cb]);
        }
        if (kc < 6) { CPW(kc + 2, (kc + 2) % 3); CPA(kc + 2, kc & 1); cp_commit(); }
        if (kc < 6) { cp_wait<1>(); }
        else if (kc == 6) { cp_wait<0>(); }
        if (kc < 7) GENX(kc + 1, (kc + 1) & 1);
        __syncthreads();
    }

    // -------- epilogue: full row sums of w3a * elu(x2 + q) --------
    float rsum[2][2];
    rsum[0][0] = rsum[0][1] = rsum[1][0] = rsum[1][1] = 0.f;
#pragma unroll
    for (int ra = 0; ra < 2; ra++) {
#pragma unroll
        for (int cb = 0; cb < 8; cb++) {
#pragma unroll
            for (int jj = 0; jj < 4; jj++) {
                int col = wc * 64 + cb * 8 + 2 * lt + (jj & 1);
                float v = acc[ra][cb][jj] + sm[SM_QS + col];
                rsum[ra][jj >> 1] += sm[SM_W3A + col] * melu(v);
            }
        }
    }
#pragma unroll
    for (int m = 1; m <= 2; m <<= 1)
#pragma unroll
        for (int ra = 0; ra < 2; ra++) {
            rsum[ra][0] += __shfl_xor_sync(0xffffffffu, rsum[ra][0], m);
            rsum[ra][1] += __shfl_xor_sync(0xffffffffu, rsum[ra][1], m);
        }
    if (lt == 0) {
#pragma unroll
        for (int ra = 0; ra < 2; ra++) {
            sm[SM_RR + wc * 64 + wr * 32 + ra * 16 + lg]     = rsum[ra][0];
            sm[SM_RR + wc * 64 + wr * 32 + ra * 16 + 8 + lg] = rsum[ra][1];
        }
    }
    __syncthreads();
    if (tid < 64)
        d_x3_g[g * 128 + mh * 64 + tid] =
            sm[SM_RR + tid] + sm[SM_RR + 64 + tid] +
            sm[SM_RR + 128 + tid] + sm[SM_RR + 192 + tid];
}

// ---- k4: + cgene, softmax over cells ----
__global__ __launch_bounds__(128) void k4(float* __restrict__ out)
{
    int g = blockIdx.x, tid = threadIdx.x;
    __shared__ float buf[128];
    float v = d_x3_g[g * 128 + tid] + d_cg_g[g];
    buf[tid] = v;
    __syncthreads();
    for (int off = 64; off > 0; off >>= 1) {
        if (tid < off) buf[tid] = fmaxf(buf[tid], buf[tid + off]);
        __syncthreads();
    }
    float m = buf[0];
    __syncthreads();
    float e = __expf(v - m);
    buf[tid] = e;
    __syncthreads();
    for (int off = 64; off > 0; off >>= 1) {
        if (tid < off) buf[tid] += buf[tid + off];
        __syncthreads();
    }
    out[tid * Gg + g] = e / buf[0];
}

// -------------------------------------------------------------------------
extern "C" void kernel_launch(void* const* d_in, const int* in_sizes, int n_in,
                              void* d_out, int out_size)
{
    const float* ctrl       = (const float*)d_in[0];
    const float* shift_vec  = (const float*)d_in[1];
    const int*   gidx       = (const int*)d_in[2];
    const float* ce_w1      = (const float*)d_in[3];
    const float* ce_b1      = (const float*)d_in[4];
    const float* ce_w2      = (const float*)d_in[5];
    const float* ce_b2      = (const float*)d_in[6];
    const float* gene_table = (const float*)d_in[7];
    const float* g_w1       = (const float*)d_in[8];
    const float* g_b1       = (const float*)d_in[9];
    const float* g_w2       = (const float*)d_in[10];
    const float* g_b2       = (const float*)d_in[11];
    const float* g_w3       = (const float*)d_in[12];
    const float* g_b3       = (const float*)d_in[13];
    float* out = (float*)d_out;

    cudaFuncSetAttribute(k3, cudaFuncAttributeMaxDynamicSharedMemorySize,
                         K3_WORDS * (int)sizeof(float));

    k_ce<<<Cc, 1024>>>(ctrl, ce_w1, ce_b1, ce_w2, ce_b2);
    k_AT<<<192, 256>>>(g_w1, g_w2);
    k_B<<<Gg, 256>>>(gidx, shift_vec, gene_table, g_w1, g_b1);
    k_p<<<Gg, 256>>>(ctrl, gidx, g_w1);
    k_q<<<Gg / 8, 512>>>(g_w2, g_b2, g_w3, g_b3);
    k3<<<2 * Gg, 256, K3_WORDS * sizeof(float)>>>(ctrl, gidx, g_w1, g_w3);
    k4<<<Gg, 128>>>(out);
}

// round 14
// speedup vs baseline: 1.3068x; 1.0486x over previous
#include <cuda_runtime.h>
#include <cuda_bf16.h>
#include <cstdint>

#define Cc 128
#define Gg 2000

// ---------------- scratch (device globals; no allocation) ----------------
__device__ float d_ce_g[Cc * 64];
__device__ float d_A_g[Cc * 256];
__device__ float d_B_g[Gg * 256];
__device__ float d_p_g[Gg * 256];
__device__ float d_q_g[Gg * 256];
__device__ float d_cg_g[Gg];
__device__ float d_x3_g[Gg * Cc];
__device__ __nv_bfloat16 d_Wt16[256 * 256];   // W2a^T bf16 [n][k]

__device__ __forceinline__ float eluf(float x) {
    return x > 0.f ? x : (__expf(x) - 1.f);
}
// branchless exact elu
__device__ __forceinline__ float melu(float x) {
    return fmaxf(x, 0.f) + __expf(fminf(x, 0.f)) - 1.f;
}

__device__ __forceinline__ void mma_bf16(float* acc, const unsigned* a, const unsigned* b) {
    asm volatile(
        "mma.sync.aligned.m16n8k16.row.col.f32.bf16.bf16.f32 "
        "{%0,%1,%2,%3}, {%4,%5,%6,%7}, {%8,%9}, {%0,%1,%2,%3};"
        : "+f"(acc[0]), "+f"(acc[1]), "+f"(acc[2]), "+f"(acc[3])
        : "r"(a[0]), "r"(a[1]), "r"(a[2]), "r"(a[3]), "r"(b[0]), "r"(b[1]));
}
__device__ __forceinline__ void ldsm4(unsigned& r0, unsigned& r1, unsigned& r2, unsigned& r3,
                                      uint32_t addr) {
    asm volatile("ldmatrix.sync.aligned.m8n8.x4.shared.b16 {%0,%1,%2,%3}, [%4];"
                 : "=r"(r0), "=r"(r1), "=r"(r2), "=r"(r3) : "r"(addr));
}
__device__ __forceinline__ uint32_t smem_u32(const void* p) {
    uint32_t a;
    asm("{ .reg .u64 t; cvta.to.shared.u64 t, %1; cvt.u32.u64 %0, t; }" : "=r"(a) : "l"(p));
    return a;
}
__device__ __forceinline__ void cpasync16(uint32_t dst, const void* src) {
    asm volatile("cp.async.cg.shared.global [%0], [%1], 16;" :: "r"(dst), "l"(src));
}
__device__ __forceinline__ void cp_commit() { asm volatile("cp.async.commit_group;"); }
template <int N> __device__ __forceinline__ void cp_wait() {
    asm volatile("cp.async.wait_group %0;" :: "n"(N));
}

// ---------------- k_ce ----------------
__global__ __launch_bounds__(1024) void k_ce(
    const float* __restrict__ ctrl, const float* __restrict__ ce_w1,
    const float* __restrict__ ce_b1, const float* __restrict__ ce_w2,
    const float* __restrict__ ce_b2)
{
    int c = blockIdx.x, tid = threadIdx.x;
    __shared__ float row[Gg];
    __shared__ float part[4][256];
    __shared__ float h1[256];
    for (int i = tid; i < Gg; i += 1024) row[i] = ctrl[c * Gg + i];
    __syncthreads();
    int sl = tid >> 8, t = tid & 255;
    float acc = 0.f;
    for (int k = sl * 500; k < sl * 500 + 500; k++)
        acc += row[k] * ce_w1[k * 256 + t];
    part[sl][t] = acc;
    __syncthreads();
    if (tid < 256) {
        float v = part[0][tid] + part[1][tid] + part[2][tid] + part[3][tid] + ce_b1[tid];
        h1[tid] = eluf(v);
    }
    __syncthreads();
    if (tid < 256) {
        int s2 = tid >> 6, e = tid & 63;
        float a2 = 0.f;
        for (int h = s2 * 64; h < s2 * 64 + 64; h++)
            a2 += h1[h] * ce_w2[h * 64 + e];
        part[s2][e] = a2;
    }
    __syncthreads();
    if (tid < 64)
        d_ce_g[c * 64 + tid] = part[0][tid] + part[1][tid] + part[2][tid] + part[3][tid] + ce_b2[tid];
}

// ---- k_AT: blocks [0,128) = k_A; blocks [128,192) = W2a transpose->bf16 ----
__global__ __launch_bounds__(256) void k_AT(const float* __restrict__ g_w1,
                                            const float* __restrict__ g_w2)
{
    __shared__ float shb[32][33];
    if (blockIdx.x < 128) {
        int c = blockIdx.x, tid = threadIdx.x;
        float* ces = &shb[0][0];
        if (tid < 64) ces[tid] = d_ce_g[c * 64 + tid];
        __syncthreads();
        float a = 0.f;
#pragma unroll 8
        for (int e = 0; e < 64; e++)
            a += ces[e] * g_w1[(1 + e) * 256 + tid];
        d_A_g[c * 256 + tid] = a;
    } else {
        int bid = blockIdx.x - 128;
        int bx = bid & 7, by = bid >> 3;
        int tx = threadIdx.x & 31, ty = threadIdx.x >> 5;
        int k0 = bx * 32, n0 = by * 32;
#pragma unroll
        for (int p = 0; p < 4; p++)
            shb[ty + 8 * p][tx] = g_w2[(k0 + ty + 8 * p) * 256 + n0 + tx];
        __syncthreads();
#pragma unroll
        for (int p = 0; p < 4; p++)
            d_Wt16[(n0 + ty + 8 * p) * 256 + k0 + tx] = __float2bfloat16(shb[tx][ty + 8 * p]);
    }
}

// ---- k_Bp: B[g,h] in regs (stored for k3), then p[g,h] = mean_c elu(...) ----
__global__ __launch_bounds__(256) void k_Bp(
    const int* __restrict__ gidx, const float* __restrict__ shift_vec,
    const float* __restrict__ gene_table, const float* __restrict__ g_w1,
    const float* __restrict__ g_b1, const float* __restrict__ ctrl)
{
    int g = blockIdx.x, tid = threadIdx.x;
    __shared__ float ges[64];
    __shared__ float shs;
    __shared__ float cs[128];
    int gs = gidx[g];
    if (tid < 64) ges[tid] = gene_table[gs * 64 + tid];
    if (tid == 0) shs = shift_vec[gs];
    if (tid < 128) cs[tid] = ctrl[tid * Gg + gs];
    __syncthreads();
    float a = g_b1[tid] + 128.0f * g_w1[130 * 256 + tid] + shs * g_w1[129 * 256 + tid];
#pragma unroll 8
    for (int e = 0; e < 64; e++)
        a += ges[e] * g_w1[(65 + e) * 256 + tid];
    d_B_g[g * 256 + tid] = a;
    float rv = g_w1[tid];
    float s = 0.f;
#pragma unroll 8
    for (int c = 0; c < 128; c++)
        s += melu(fmaf(cs[c], rv, d_A_g[c * 256 + tid] + a));
    d_p_g[g * 256 + tid] = s * (1.f / 128.f);
}

// ---- k_q (split-k, 512 thr): q = p@W2b + b2 ; p2 = p@W2a + q ; cgene ----
__global__ __launch_bounds__(512) void k_q(
    const float* __restrict__ g_w2, const float* __restrict__ g_b2,
    const float* __restrict__ g_w3, const float* __restrict__ g_b3)
{
    __shared__ float ps[8][256];
    __shared__ float qpart[2][8][256];
    __shared__ float ppart[2][8][256];
    int g0 = blockIdx.x * 8, tid = threadIdx.x;
    for (int i = tid; i < 2048; i += 512)
        ps[i >> 8][i & 255] = d_p_g[(g0 + (i >> 8)) * 256 + (i & 255)];
    __syncthreads();
    int n = tid & 255, kh = tid >> 8;
    float qa[8], pa[8];
#pragma unroll
    for (int i = 0; i < 8; i++) { qa[i] = 0.f; pa[i] = 0.f; }
    for (int k = kh * 128; k < kh * 128 + 128; k++) {
        float wa = g_w2[k * 256 + n];
        float wb = g_w2[(256 + k) * 256 + n];
#pragma unroll
        for (int i = 0; i < 8; i++) {
            float pv = ps[i][k];
            qa[i] = fmaf(pv, wb, qa[i]);
            pa[i] = fmaf(pv, wa, pa[i]);
        }
    }
#pragma unroll
    for (int i = 0; i < 8; i++) {
        qpart[kh][i][n] = qa[i];
        ppart[kh][i][n] = pa[i];
    }
    __syncthreads();
    if (tid < 256) {
        float b2v = g_b2[tid];
        float w3bv = g_w3[256 + tid];
#pragma unroll
        for (int i = 0; i < 8; i++) {
            float q = qpart[0][i][tid] + qpart[1][i][tid] + b2v;
            d_q_g[(g0 + i) * 256 + tid] = q;
            float p2 = ppart[0][i][tid] + ppart[1][i][tid] + q;
            ps[i][tid] = w3bv * eluf(p2);
        }
    }
    __syncthreads();
    for (int off = 128; off > 0; off >>= 1) {
        if (tid < off)
#pragma unroll
            for (int i = 0; i < 8; i++) ps[i][tid] += ps[i][tid + off];
        __syncthreads();
    }
    if (tid < 8) d_cg_g[g0 + tid] = ps[tid][0] + g_b3[0];
}

// ======= k3: per-(gene, M-half) bf16 GEMM via ldmatrix + mma.m16n8k16 =====
// (proven 264.7 us configuration; only cp.async .ca -> .cg changed)
#define WBASE   0
#define WBUFW   5120
#define XBASE   15360
#define XBUFW   1280
#define ABASE   17920
#define ABUFW   2304
#define SM_CTRL 22528
#define SM_RS   22592
#define SM_BS   22848
#define SM_QS   23104
#define SM_W3A  23360
#define SM_RR   23616
#define K3_WORDS 23872   // 95488 bytes

__global__ __launch_bounds__(256, 2) void k3(
    const float* __restrict__ ctrl, const int* __restrict__ gidx,
    const float* __restrict__ g_w1, const float* __restrict__ g_w3)
{
    extern __shared__ float sm[];
    unsigned* usm = (unsigned*)sm;
    uint32_t sbase = smem_u32(sm);

    int bi = blockIdx.x;
    int g = bi >> 1, mh = bi & 1;
    int tid = threadIdx.x;
    int lane = tid & 31, w = tid >> 5;
    int lg = lane >> 2, lt = lane & 3;
    int wr = w >> 2, wc = w & 3;          // 2 x 4 warps; warp tile 32 rows x 64 cols
    int m8 = lane >> 3, r8 = lane & 7;
    int gs = gidx[g];

    // prologue scalars
    if (tid < 64) sm[SM_CTRL + tid] = ctrl[(mh * 64 + tid) * Gg + gs];
    sm[SM_RS + tid]  = g_w1[tid];
    sm[SM_BS + tid]  = d_B_g[g * 256 + tid];
    sm[SM_QS + tid]  = d_q_g[g * 256 + tid];
    sm[SM_W3A + tid] = g_w3[tid];

    auto CPW = [&](int kc, int buf) {
        for (int i = tid; i < 1024; i += 256) {
            int row = i >> 2, seg = i & 3;
            cpasync16(sbase + (WBASE + buf * WBUFW + row * 20 + seg * 4) * 4,
                      d_Wt16 + row * 256 + kc * 32 + seg * 8);
        }
    };
    auto CPA = [&](int kc, int buf) {
        for (int i = tid; i < 512; i += 256) {
            int row = i >> 3, seg = i & 7;
            cpasync16(sbase + (ABASE + buf * ABUFW + row * 36 + seg * 4) * 4,
                      d_A_g + (mh * 64 + row) * 256 + kc * 32 + seg * 4);
        }
    };
    auto GENX = [&](int kc, int xbuf) {
        int xw = XBASE + xbuf * XBUFW;
        int ab = ABASE + (kc & 1) * ABUFW;
        int kp = tid & 15, cb0 = tid >> 4;
        int h0 = kc * 32 + 2 * kp;
        float2 rsv = *(float2*)(sm + SM_RS + h0);
        float2 bsv = *(float2*)(sm + SM_BS + h0);
#pragma unroll
        for (int j = 0; j < 4; j++) {
            int c = cb0 + 16 * j;
            float cv = sm[SM_CTRL + c];
            float2 av = *(float2*)(sm + ab + c * 36 + 2 * kp);
            float v0 = melu(fmaf(cv, rsv.x, av.x + bsv.x));
            float v1 = melu(fmaf(cv, rsv.y, av.y + bsv.y));
            unsigned pr;
            asm("cvt.rn.bf16x2.f32 %0, %1, %2;" : "=r"(pr) : "f"(v1), "f"(v0));
            usm[xw + c * 20 + kp] = pr;
        }
    };

    CPW(0, 0); CPA(0, 0); cp_commit();
    CPW(1, 1); CPA(1, 1); cp_commit();
    cp_wait<1>();
    __syncthreads();     // scalars + chunk-0 copies visible
    GENX(0, 0);
    __syncthreads();

    float acc[2][8][4];
#pragma unroll
    for (int i = 0; i < 2; i++)
#pragma unroll
        for (int j = 0; j < 8; j++)
#pragma unroll
            for (int k = 0; k < 4; k++) acc[i][j][k] = 0.f;

#pragma unroll
    for (int kc = 0; kc < 8; kc++) {
        uint32_t xbb = sbase + (XBASE + (kc & 1) * XBUFW) * 4;
        uint32_t wbb = sbase + (WBASE + (kc % 3) * WBUFW) * 4;
#pragma unroll
        for (int ks = 0; ks < 2; ks++) {
            int k0b = ks * 32;
            unsigned a[2][4], b[8][2];
#pragma unroll
            for (int ra = 0; ra < 2; ra++) {
                uint32_t addr = xbb + (wr * 32 + ra * 16 + (m8 & 1) * 8 + r8) * 80
                              + k0b + (m8 >> 1) * 16;
                ldsm4(a[ra][0], a[ra][1], a[ra][2], a[ra][3], addr);
            }
#pragma unroll
            for (int cbp = 0; cbp < 4; cbp++) {
                uint32_t addr = wbb + (wc * 64 + (2 * cbp + (m8 >> 1)) * 8 + r8) * 80
                              + k0b + (m8 & 1) * 16;
                ldsm4(b[2 * cbp][0], b[2 * cbp][1], b[2 * cbp + 1][0], b[2 * cbp + 1][1], addr);
            }
#pragma unroll
            for (int ra = 0; ra < 2; ra++)
#pragma unroll
                for (int cb = 0; cb < 8; cb++)
                    mma_bf16(acc[ra][cb], a[ra], b[cb]);
        }
        if (kc < 6) { CPW(kc + 2, (kc + 2) % 3); CPA(kc + 2, kc & 1); cp_commit(); }
        if (kc < 6) { cp_wait<1>(); }
        else if (kc == 6) { cp_wait<0>(); }
        if (kc < 7) GENX(kc + 1, (kc + 1) & 1);
        __syncthreads();
    }

    // -------- epilogue: full row sums of w3a * elu(x2 + q) --------
    float rsum[2][2];
    rsum[0][0] = rsum[0][1] = rsum[1][0] = rsum[1][1] = 0.f;
#pragma unroll
    for (int ra = 0; ra < 2; ra++) {
#pragma unroll
        for (int cb = 0; cb < 8; cb++) {
#pragma unroll
            for (int jj = 0; jj < 4; jj++) {
                int col = wc * 64 + cb * 8 + 2 * lt + (jj & 1);
                float v = acc[ra][cb][jj] + sm[SM_QS + col];
                rsum[ra][jj >> 1] += sm[SM_W3A + col] * melu(v);
            }
        }
    }
#pragma unroll
    for (int m = 1; m <= 2; m <<= 1)
#pragma unroll
        for (int ra = 0; ra < 2; ra++) {
            rsum[ra][0] += __shfl_xor_sync(0xffffffffu, rsum[ra][0], m);
            rsum[ra][1] += __shfl_xor_sync(0xffffffffu, rsum[ra][1], m);
        }
    if (lt == 0) {
#pragma unroll
        for (int ra = 0; ra < 2; ra++) {
            sm[SM_RR + wc * 64 + wr * 32 + ra * 16 + lg]     = rsum[ra][0];
            sm[SM_RR + wc * 64 + wr * 32 + ra * 16 + 8 + lg] = rsum[ra][1];
        }
    }
    __syncthreads();
    if (tid < 64)
        d_x3_g[g * 128 + mh * 64 + tid] =
            sm[SM_RR + tid] + sm[SM_RR + 64 + tid] +
            sm[SM_RR + 128 + tid] + sm[SM_RR + 192 + tid];
}

// ---- k4: + cgene, softmax over cells ----
__global__ __launch_bounds__(128) void k4(float* __restrict__ out)
{
    int g = blockIdx.x, tid = threadIdx.x;
    __shared__ float buf[128];
    float v = d_x3_g[g * 128 + tid] + d_cg_g[g];
    buf[tid] = v;
    __syncthreads();
    for (int off = 64; off > 0; off >>= 1) {
        if (tid < off) buf[tid] = fmaxf(buf[tid], buf[tid + off]);
        __syncthreads();
    }
    float m = buf[0];
    __syncthreads();
    float e = __expf(v - m);
    buf[tid] = e;
    __syncthreads();
    for (int off = 64; off > 0; off >>= 1) {
        if (tid < off) buf[tid] += buf[tid + off];
        __syncthreads();
    }
    out[tid * Gg + g] = e / buf[0];
}

// -------------------------------------------------------------------------
extern "C" void kernel_launch(void* const* d_in, const int* in_sizes, int n_in,
                              void* d_out, int out_size)
{
    const float* ctrl       = (const float*)d_in[0];
    const float* shift_vec  = (const float*)d_in[1];
    const int*   gidx       = (const int*)d_in[2];
    const float* ce_w1      = (const float*)d_in[3];
    const float* ce_b1      = (const float*)d_in[4];
    const float* ce_w2      = (const float*)d_in[5];
    const float* ce_b2      = (const float*)d_in[6];
    const float* gene_table = (const float*)d_in[7];
    const float* g_w1       = (const float*)d_in[8];
    const float* g_b1       = (const float*)d_in[9];
    const float* g_w2       = (const float*)d_in[10];
    const float* g_b2       = (const float*)d_in[11];
    const float* g_w3       = (const float*)d_in[12];
    const float* g_b3       = (const float*)d_in[13];
    float* out = (float*)d_out;

    cudaFuncSetAttribute(k3, cudaFuncAttributeMaxDynamicSharedMemorySize,
                         K3_WORDS * (int)sizeof(float));

    k_ce<<<Cc, 1024>>>(ctrl, ce_w1, ce_b1, ce_w2, ce_b2);
    k_AT<<<192, 256>>>(g_w1, g_w2);
    k_Bp<<<Gg, 256>>>(gidx, shift_vec, gene_table, g_w1, g_b1, ctrl);
    k_q<<<Gg / 8, 512>>>(g_w2, g_b2, g_w3, g_b3);
    k3<<<2 * Gg, 256, K3_WORDS * sizeof(float)>>>(ctrl, gidx, g_w1, g_w3);
    k4<<<Gg, 128>>>(out);
}

// round 15
// speedup vs baseline: 1.3649x; 1.0445x over previous
#include <cuda_runtime.h>
#include <cuda_bf16.h>
#include <cstdint>

#define Cc 128
#define Gg 2000

// ---------------- scratch (device globals; no allocation) ----------------
__device__ float d_ce_g[Cc * 64];
__device__ float d_A_g[Cc * 256];
__device__ float d_B_g[Gg * 256];
__device__ float d_p_g[Gg * 256];
__device__ float d_q_g[Gg * 256];
__device__ float d_x3_g[Gg * Cc];
__device__ __nv_bfloat16 d_Wt16[256 * 256];   // W2a^T bf16 [n][k]

__device__ __forceinline__ float eluf(float x) {
    return x > 0.f ? x : (__expf(x) - 1.f);
}
// branchless exact elu
__device__ __forceinline__ float melu(float x) {
    return fmaxf(x, 0.f) + __expf(fminf(x, 0.f)) - 1.f;
}

__device__ __forceinline__ void mma_bf16(float* acc, const unsigned* a, const unsigned* b) {
    asm volatile(
        "mma.sync.aligned.m16n8k16.row.col.f32.bf16.bf16.f32 "
        "{%0,%1,%2,%3}, {%4,%5,%6,%7}, {%8,%9}, {%0,%1,%2,%3};"
        : "+f"(acc[0]), "+f"(acc[1]), "+f"(acc[2]), "+f"(acc[3])
        : "r"(a[0]), "r"(a[1]), "r"(a[2]), "r"(a[3]), "r"(b[0]), "r"(b[1]));
}
__device__ __forceinline__ void ldsm4(unsigned& r0, unsigned& r1, unsigned& r2, unsigned& r3,
                                      uint32_t addr) {
    asm volatile("ldmatrix.sync.aligned.m8n8.x4.shared.b16 {%0,%1,%2,%3}, [%4];"
                 : "=r"(r0), "=r"(r1), "=r"(r2), "=r"(r3) : "r"(addr));
}
__device__ __forceinline__ uint32_t smem_u32(const void* p) {
    uint32_t a;
    asm("{ .reg .u64 t; cvta.to.shared.u64 t, %1; cvt.u32.u64 %0, t; }" : "=r"(a) : "l"(p));
    return a;
}
__device__ __forceinline__ void cpasync16(uint32_t dst, const void* src) {
    asm volatile("cp.async.cg.shared.global [%0], [%1], 16;" :: "r"(dst), "l"(src));
}
__device__ __forceinline__ void cp_commit() { asm volatile("cp.async.commit_group;"); }
template <int N> __device__ __forceinline__ void cp_wait() {
    asm volatile("cp.async.wait_group %0;" :: "n"(N));
}

// ---------------- k_ce ----------------
__global__ __launch_bounds__(1024) void k_ce(
    const float* __restrict__ ctrl, const float* __restrict__ ce_w1,
    const float* __restrict__ ce_b1, const float* __restrict__ ce_w2,
    const float* __restrict__ ce_b2)
{
    int c = blockIdx.x, tid = threadIdx.x;
    __shared__ float row[Gg];
    __shared__ float part[4][256];
    __shared__ float h1[256];
    for (int i = tid; i < Gg; i += 1024) row[i] = ctrl[c * Gg + i];
    __syncthreads();
    int sl = tid >> 8, t = tid & 255;
    float acc = 0.f;
    for (int k = sl * 500; k < sl * 500 + 500; k++)
        acc += row[k] * ce_w1[k * 256 + t];
    part[sl][t] = acc;
    __syncthreads();
    if (tid < 256) {
        float v = part[0][tid] + part[1][tid] + part[2][tid] + part[3][tid] + ce_b1[tid];
        h1[tid] = eluf(v);
    }
    __syncthreads();
    if (tid < 256) {
        int s2 = tid >> 6, e = tid & 63;
        float a2 = 0.f;
        for (int h = s2 * 64; h < s2 * 64 + 64; h++)
            a2 += h1[h] * ce_w2[h * 64 + e];
        part[s2][e] = a2;
    }
    __syncthreads();
    if (tid < 64)
        d_ce_g[c * 64 + tid] = part[0][tid] + part[1][tid] + part[2][tid] + part[3][tid] + ce_b2[tid];
}

// ---- k_AT: blocks [0,128) = k_A; blocks [128,192) = W2a transpose->bf16 ----
__global__ __launch_bounds__(256) void k_AT(const float* __restrict__ g_w1,
                                            const float* __restrict__ g_w2)
{
    __shared__ float shb[32][33];
    if (blockIdx.x < 128) {
        int c = blockIdx.x, tid = threadIdx.x;
        float* ces = &shb[0][0];
        if (tid < 64) ces[tid] = d_ce_g[c * 64 + tid];
        __syncthreads();
        float a = 0.f;
#pragma unroll 8
        for (int e = 0; e < 64; e++)
            a += ces[e] * g_w1[(1 + e) * 256 + tid];
        d_A_g[c * 256 + tid] = a;
    } else {
        int bid = blockIdx.x - 128;
        int bx = bid & 7, by = bid >> 3;
        int tx = threadIdx.x & 31, ty = threadIdx.x >> 5;
        int k0 = bx * 32, n0 = by * 32;
#pragma unroll
        for (int p = 0; p < 4; p++)
            shb[ty + 8 * p][tx] = g_w2[(k0 + ty + 8 * p) * 256 + n0 + tx];
        __syncthreads();
#pragma unroll
        for (int p = 0; p < 4; p++)
            d_Wt16[(n0 + ty + 8 * p) * 256 + k0 + tx] = __float2bfloat16(shb[tx][ty + 8 * p]);
    }
}

// ---- k_Bp: 2 genes/block. B in regs (stored), p = mean_c elu(...) --------
__global__ __launch_bounds__(256) void k_Bp(
    const int* __restrict__ gidx, const float* __restrict__ shift_vec,
    const float* __restrict__ gene_table, const float* __restrict__ g_w1,
    const float* __restrict__ g_b1, const float* __restrict__ ctrl)
{
    int g0 = blockIdx.x * 2, tid = threadIdx.x;
    __shared__ float ges[2][64];
    __shared__ float shs[2];
    __shared__ float cs[2][128];
    int gs0 = gidx[g0], gs1 = gidx[g0 + 1];
    if (tid < 64)       ges[0][tid] = gene_table[gs0 * 64 + tid];
    else if (tid < 128) ges[1][tid - 64] = gene_table[gs1 * 64 + (tid - 64)];
    if (tid == 0) shs[0] = shift_vec[gs0];
    if (tid == 1) shs[1] = shift_vec[gs1];
    if (tid < 128) {
        cs[0][tid] = ctrl[tid * Gg + gs0];
        cs[1][tid] = ctrl[tid * Gg + gs1];
    }
    __syncthreads();
    float base = g_b1[tid] + 128.0f * g_w1[130 * 256 + tid];
    float w129 = g_w1[129 * 256 + tid];
    float a0 = base + shs[0] * w129;
    float a1 = base + shs[1] * w129;
#pragma unroll 8
    for (int e = 0; e < 64; e++) {
        float wv = g_w1[(65 + e) * 256 + tid];
        a0 = fmaf(ges[0][e], wv, a0);
        a1 = fmaf(ges[1][e], wv, a1);
    }
    d_B_g[g0 * 256 + tid]       = a0;
    d_B_g[(g0 + 1) * 256 + tid] = a1;
    float rv = g_w1[tid];
    float s0 = 0.f, s1 = 0.f;
#pragma unroll 8
    for (int c = 0; c < 128; c++) {
        float Av = d_A_g[c * 256 + tid];
        s0 += melu(fmaf(cs[0][c], rv, Av + a0));
        s1 += melu(fmaf(cs[1][c], rv, Av + a1));
    }
    d_p_g[g0 * 256 + tid]       = s0 * (1.f / 128.f);
    d_p_g[(g0 + 1) * 256 + tid] = s1 * (1.f / 128.f);
}

// ---- k_q (split-k, 512 thr): q = p@W2b + b2  (cgene term cancels in softmax) ----
__global__ __launch_bounds__(512) void k_q(
    const float* __restrict__ g_w2, const float* __restrict__ g_b2)
{
    __shared__ float ps[8][256];
    __shared__ float qpart[2][8][256];
    int g0 = blockIdx.x * 8, tid = threadIdx.x;
    for (int i = tid; i < 2048; i += 512)
        ps[i >> 8][i & 255] = d_p_g[(g0 + (i >> 8)) * 256 + (i & 255)];
    __syncthreads();
    int n = tid & 255, kh = tid >> 8;
    float qa[8];
#pragma unroll
    for (int i = 0; i < 8; i++) qa[i] = 0.f;
    for (int k = kh * 128; k < kh * 128 + 128; k++) {
        float wb = g_w2[(256 + k) * 256 + n];
#pragma unroll
        for (int i = 0; i < 8; i++)
            qa[i] = fmaf(ps[i][k], wb, qa[i]);
    }
#pragma unroll
    for (int i = 0; i < 8; i++) qpart[kh][i][n] = qa[i];
    __syncthreads();
    if (tid < 256) {
        float b2v = g_b2[tid];
#pragma unroll
        for (int i = 0; i < 8; i++)
            d_q_g[(g0 + i) * 256 + tid] = qpart[0][i][tid] + qpart[1][i][tid] + b2v;
    }
}

// ======= k3: per-(gene, M-half) bf16 GEMM via ldmatrix + mma.m16n8k16 =====
// (proven 252.4 us configuration; untouched)
#define WBASE   0
#define WBUFW   5120
#define XBASE   15360
#define XBUFW   1280
#define ABASE   17920
#define ABUFW   2304
#define SM_CTRL 22528
#define SM_RS   22592
#define SM_BS   22848
#define SM_QS   23104
#define SM_W3A  23360
#define SM_RR   23616
#define K3_WORDS 23872   // 95488 bytes

__global__ __launch_bounds__(256, 2) void k3(
    const float* __restrict__ ctrl, const int* __restrict__ gidx,
    const float* __restrict__ g_w1, const float* __restrict__ g_w3)
{
    extern __shared__ float sm[];
    unsigned* usm = (unsigned*)sm;
    uint32_t sbase = smem_u32(sm);

    int bi = blockIdx.x;
    int g = bi >> 1, mh = bi & 1;
    int tid = threadIdx.x;
    int lane = tid & 31, w = tid >> 5;
    int lg = lane >> 2, lt = lane & 3;
    int wr = w >> 2, wc = w & 3;          // 2 x 4 warps; warp tile 32 rows x 64 cols
    int m8 = lane >> 3, r8 = lane & 7;
    int gs = gidx[g];

    // prologue scalars
    if (tid < 64) sm[SM_CTRL + tid] = ctrl[(mh * 64 + tid) * Gg + gs];
    sm[SM_RS + tid]  = g_w1[tid];
    sm[SM_BS + tid]  = d_B_g[g * 256 + tid];
    sm[SM_QS + tid]  = d_q_g[g * 256 + tid];
    sm[SM_W3A + tid] = g_w3[tid];

    auto CPW = [&](int kc, int buf) {
        for (int i = tid; i < 1024; i += 256) {
            int row = i >> 2, seg = i & 3;
            cpasync16(sbase + (WBASE + buf * WBUFW + row * 20 + seg * 4) * 4,
                      d_Wt16 + row * 256 + kc * 32 + seg * 8);
        }
    };
    auto CPA = [&](int kc, int buf) {
        for (int i = tid; i < 512; i += 256) {
            int row = i >> 3, seg = i & 7;
            cpasync16(sbase + (ABASE + buf * ABUFW + row * 36 + seg * 4) * 4,
                      d_A_g + (mh * 64 + row) * 256 + kc * 32 + seg * 4);
        }
    };
    auto GENX = [&](int kc, int xbuf) {
        int xw = XBASE + xbuf * XBUFW;
        int ab = ABASE + (kc & 1) * ABUFW;
        int kp = tid & 15, cb0 = tid >> 4;
        int h0 = kc * 32 + 2 * kp;
        float2 rsv = *(float2*)(sm + SM_RS + h0);
        float2 bsv = *(float2*)(sm + SM_BS + h0);
#pragma unroll
        for (int j = 0; j < 4; j++) {
            int c = cb0 + 16 * j;
            float cv = sm[SM_CTRL + c];
            float2 av = *(float2*)(sm + ab + c * 36 + 2 * kp);
            float v0 = melu(fmaf(cv, rsv.x, av.x + bsv.x));
            float v1 = melu(fmaf(cv, rsv.y, av.y + bsv.y));
            unsigned pr;
            asm("cvt.rn.bf16x2.f32 %0, %1, %2;" : "=r"(pr) : "f"(v1), "f"(v0));
            usm[xw + c * 20 + kp] = pr;
        }
    };

    CPW(0, 0); CPA(0, 0); cp_commit();
    CPW(1, 1); CPA(1, 1); cp_commit();
    cp_wait<1>();
    __syncthreads();     // scalars + chunk-0 copies visible
    GENX(0, 0);
    __syncthreads();

    float acc[2][8][4];
#pragma unroll
    for (int i = 0; i < 2; i++)
#pragma unroll
        for (int j = 0; j < 8; j++)
#pragma unroll
            for (int k = 0; k < 4; k++) acc[i][j][k] = 0.f;

#pragma unroll
    for (int kc = 0; kc < 8; kc++) {
        uint32_t xbb = sbase + (XBASE + (kc & 1) * XBUFW) * 4;
        uint32_t wbb = sbase + (WBASE + (kc % 3) * WBUFW) * 4;
#pragma unroll
        for (int ks = 0; ks < 2; ks++) {
            int k0b = ks * 32;
            unsigned a[2][4], b[8][2];
#pragma unroll
            for (int ra = 0; ra < 2; ra++) {
                uint32_t addr = xbb + (wr * 32 + ra * 16 + (m8 & 1) * 8 + r8) * 80
                              + k0b + (m8 >> 1) * 16;
                ldsm4(a[ra][0], a[ra][1], a[ra][2], a[ra][3], addr);
            }
#pragma unroll
            for (int cbp = 0; cbp < 4; cbp++) {
                uint32_t addr = wbb + (wc * 64 + (2 * cbp + (m8 >> 1)) * 8 + r8) * 80
                              + k0b + (m8 & 1) * 16;
                ldsm4(b[2 * cbp][0], b[2 * cbp][1], b[2 * cbp + 1][0], b[2 * cbp + 1][1], addr);
            }
#pragma unroll
            for (int ra = 0; ra < 2; ra++)
#pragma unroll
                for (int cb = 0; cb < 8; cb++)
                    mma_bf16(acc[ra][cb], a[ra], b[cb]);
        }
        if (kc < 6) { CPW(kc + 2, (kc + 2) % 3); CPA(kc + 2, kc & 1); cp_commit(); }
        if (kc < 6) { cp_wait<1>(); }
        else if (kc == 6) { cp_wait<0>(); }
        if (kc < 7) GENX(kc + 1, (kc + 1) & 1);
        __syncthreads();
    }

    // -------- epilogue: full row sums of w3a * elu(x2 + q) --------
    float rsum[2][2];
    rsum[0][0] = rsum[0][1] = rsum[1][0] = rsum[1][1] = 0.f;
#pragma unroll
    for (int ra = 0; ra < 2; ra++) {
#pragma unroll
        for (int cb = 0; cb < 8; cb++) {
#pragma unroll
            for (int jj = 0; jj < 4; jj++) {
                int col = wc * 64 + cb * 8 + 2 * lt + (jj & 1);
                float v = acc[ra][cb][jj] + sm[SM_QS + col];
                rsum[ra][jj >> 1] += sm[SM_W3A + col] * melu(v);
            }
        }
    }
#pragma unroll
    for (int m = 1; m <= 2; m <<= 1)
#pragma unroll
        for (int ra = 0; ra < 2; ra++) {
            rsum[ra][0] += __shfl_xor_sync(0xffffffffu, rsum[ra][0], m);
            rsum[ra][1] += __shfl_xor_sync(0xffffffffu, rsum[ra][1], m);
        }
    if (lt == 0) {
#pragma unroll
        for (int ra = 0; ra < 2; ra++) {
            sm[SM_RR + wc * 64 + wr * 32 + ra * 16 + lg]     = rsum[ra][0];
            sm[SM_RR + wc * 64 + wr * 32 + ra * 16 + 8 + lg] = rsum[ra][1];
        }
    }
    __syncthreads();
    if (tid < 64)
        d_x3_g[g * 128 + mh * 64 + tid] =
            sm[SM_RR + tid] + sm[SM_RR + 64 + tid] +
            sm[SM_RR + 128 + tid] + sm[SM_RR + 192 + tid];
}

// ---- k4: softmax over cells (cgene/b3 cancel in softmax) ----
__global__ __launch_bounds__(128) void k4(float* __restrict__ out)
{
    int g = blockIdx.x, tid = threadIdx.x;
    __shared__ float buf[128];
    float v = d_x3_g[g * 128 + tid];
    buf[tid] = v;
    __syncthreads();
    for (int off = 64; off > 0; off >>= 1) {
        if (tid < off) buf[tid] = fmaxf(buf[tid], buf[tid + off]);
        __syncthreads();
    }
    float m = buf[0];
    __syncthreads();
    float e = __expf(v - m);
    buf[tid] = e;
    __syncthreads();
    for (int off = 64; off > 0; off >>= 1) {
        if (tid < off) buf[tid] += buf[tid + off];
        __syncthreads();
    }
    out[tid * Gg + g] = e / buf[0];
}

// -------------------------------------------------------------------------
extern "C" void kernel_launch(void* const* d_in, const int* in_sizes, int n_in,
                              void* d_out, int out_size)
{
    const float* ctrl       = (const float*)d_in[0];
    const float* shift_vec  = (const float*)d_in[1];
    const int*   gidx       = (const int*)d_in[2];
    const float* ce_w1      = (const float*)d_in[3];
    const float* ce_b1      = (const float*)d_in[4];
    const float* ce_w2      = (const float*)d_in[5];
    const float* ce_b2      = (const float*)d_in[6];
    const float* gene_table = (const float*)d_in[7];
    const float* g_w1       = (const float*)d_in[8];
    const float* g_b1       = (const float*)d_in[9];
    const float* g_w2       = (const float*)d_in[10];
    const float* g_b2       = (const float*)d_in[11];
    const float* g_w3       = (const float*)d_in[12];
    const float* g_b3       = (const float*)d_in[13];
    float* out = (float*)d_out;

    cudaFuncSetAttribute(k3, cudaFuncAttributeMaxDynamicSharedMemorySize,
                         K3_WORDS * (int)sizeof(float));

    k_ce<<<Cc, 1024>>>(ctrl, ce_w1, ce_b1, ce_w2, ce_b2);
    k_AT<<<192, 256>>>(g_w1, g_w2);
    k_Bp<<<Gg / 2, 256>>>(gidx, shift_vec, gene_table, g_w1, g_b1, ctrl);
    k_q<<<Gg / 8, 512>>>(g_w2, g_b2);
    k3<<<2 * Gg, 256, K3_WORDS * sizeof(float)>>>(ctrl, gidx, g_w1, g_w3);
    k4<<<Gg, 128>>>(out);
}